// round 1
// baseline (speedup 1.0000x reference)
#include <cuda_runtime.h>
#include <cuda_fp16.h>
#include <cstdint>

// Problem dims (fixed by the dataset)
#define D_DIM 4096
#define H_DIM 11008
#define T_MAX 8192

// NF4 lookup table (compile-time constant memory, no runtime copy needed)
__device__ __constant__ float c_nf4[16] = {
    -1.0f, -0.6961928009986877f, -0.5250730514526367f, -0.39491748809814453f,
    -0.28444138169288635f, -0.18477343022823334f, -0.09105003625154495f, 0.0f,
    0.07958029955625534f, 0.16093020141124725f, 0.24611230194568634f,
    0.33791524171829224f, 0.44070982933044434f, 0.5626170039176941f,
    0.7229568362236023f, 1.0f};

// Scratch (static __device__ arrays: allocation-guard safe)
__device__ __half g_w1[(size_t)H_DIM * D_DIM];
__device__ __half g_w2[(size_t)H_DIM * D_DIM];
__device__ __half g_w3[(size_t)D_DIM * H_DIM];
__device__ __half g_x [(size_t)T_MAX * D_DIM];
__device__ float  g_s1[(size_t)T_MAX * H_DIM];
__device__ __half g_h [(size_t)T_MAX * H_DIM];

// ---------------------------------------------------------------------------
// Dequant: codes int32 [n], scalers per 64-elem block -> fp16
// ---------------------------------------------------------------------------
__global__ void dequant_nf4_kernel(const int* __restrict__ codes,
                                   const float* __restrict__ scalers,
                                   __half* __restrict__ out, int n4) {
    int i = blockIdx.x * blockDim.x + threadIdx.x;
    if (i >= n4) return;
    int4 c = ((const int4*)codes)[i];
    float s = __ldg(&scalers[i >> 4]);  // (i*4)/64
    __half2 h0 = __floats2half2_rn(c_nf4[c.x & 15] * s, c_nf4[c.y & 15] * s);
    __half2 h1 = __floats2half2_rn(c_nf4[c.z & 15] * s, c_nf4[c.w & 15] * s);
    ((__half2*)out)[2 * i]     = h0;
    ((__half2*)out)[2 * i + 1] = h1;
}

__global__ void f32_to_f16_kernel(const float* __restrict__ in,
                                  __half* __restrict__ out, int n4) {
    int i = blockIdx.x * blockDim.x + threadIdx.x;
    if (i >= n4) return;
    float4 v = ((const float4*)in)[i];
    ((__half2*)out)[2 * i]     = __floats2half2_rn(v.x, v.y);
    ((__half2*)out)[2 * i + 1] = __floats2half2_rn(v.z, v.w);
}

// ---------------------------------------------------------------------------
// GEMM: C[M,N] = A[M,K] * B[N,K]^T   (A row-major, B row-major "TN" layout)
// CTA tile 128x128x64, 8 warps (2x4), warp tile 64x32, mma.m16n8k16 fp16->fp32
// EPI=0: store fp32 to C.   EPI=1: read aux fp32 (s1), C = half(silu(aux)*acc)
// ---------------------------------------------------------------------------
#define BM 128
#define BN 128
#define BK 64

__device__ __forceinline__ void cp_async16(uint32_t dst, const void* src) {
    asm volatile("cp.async.cg.shared.global [%0], [%1], 16;\n" ::"r"(dst), "l"(src));
}

template <int EPI>
__global__ void __launch_bounds__(256, 2) gemm_kernel(
    const __half* __restrict__ A, const __half* __restrict__ B,
    void* __restrict__ Cout, const float* __restrict__ aux,
    int M, int N, int K) {
    extern __shared__ __align__(128) char smem_raw[];
    const int A_BYTES = BM * BK * 2;            // 16 KB
    const int STAGE_BYTES = (BM + BN) * BK * 2; // 32 KB
    uint32_t smem_base = (uint32_t)__cvta_generic_to_shared(smem_raw);

    int tid  = threadIdx.x;
    int lane = tid & 31;
    int warp = tid >> 5;
    int wrow = warp >> 2;  // 0..1 -> 64 rows each
    int wcol = warp & 3;   // 0..3 -> 32 cols each

    long bm0 = (long)blockIdx.y * BM;
    long bn0 = (long)blockIdx.x * BN;

    const __half* Ablk = A + bm0 * K;
    const __half* Bblk = B + bn0 * K;

    int KT = K / BK;

    auto load_stage = [&](int kt, int s) {
        uint32_t sa = smem_base + s * STAGE_BYTES;
        uint32_t sb = sa + A_BYTES;
        long koff = (long)kt * BK;
#pragma unroll
        for (int i = 0; i < 4; i++) {
            int e = i * 256 + tid;
            int row = e >> 3;
            int chunk = e & 7;
            uint32_t dst = sa + row * 128 + ((chunk * 16) ^ ((row & 7) * 16));
            cp_async16(dst, Ablk + (long)row * K + koff + chunk * 8);
        }
#pragma unroll
        for (int i = 0; i < 4; i++) {
            int e = i * 256 + tid;
            int row = e >> 3;
            int chunk = e & 7;
            uint32_t dst = sb + row * 128 + ((chunk * 16) ^ ((row & 7) * 16));
            cp_async16(dst, Bblk + (long)row * K + koff + chunk * 8);
        }
        asm volatile("cp.async.commit_group;\n");
    };

    float acc[4][4][4];
#pragma unroll
    for (int mt = 0; mt < 4; mt++)
#pragma unroll
        for (int nt = 0; nt < 4; nt++)
#pragma unroll
            for (int r = 0; r < 4; r++) acc[mt][nt][r] = 0.f;

    load_stage(0, 0);

    for (int kt = 0; kt < KT; kt++) {
        if (kt + 1 < KT) {
            load_stage(kt + 1, (kt + 1) & 1);
            asm volatile("cp.async.wait_group 1;\n");
        } else {
            asm volatile("cp.async.wait_group 0;\n");
        }
        __syncthreads();

        uint32_t sa = smem_base + (kt & 1) * STAGE_BYTES;
        uint32_t sb = sa + A_BYTES;
#pragma unroll
        for (int k16 = 0; k16 < BK / 16; k16++) {
            uint32_t a[4][4];
            uint32_t b[4][2];
#pragma unroll
            for (int mt = 0; mt < 4; mt++) {
                int row = wrow * 64 + mt * 16 + (lane & 15);
                int colh = k16 * 16 + (lane >> 4) * 8;
                uint32_t addr = sa + row * 128 + ((colh * 2) ^ ((row & 7) * 16));
                asm volatile(
                    "ldmatrix.sync.aligned.m8n8.x4.shared.b16 {%0,%1,%2,%3}, [%4];"
                    : "=r"(a[mt][0]), "=r"(a[mt][1]), "=r"(a[mt][2]), "=r"(a[mt][3])
                    : "r"(addr));
            }
#pragma unroll
            for (int nt = 0; nt < 4; nt++) {
                int l = lane & 15;
                int row = wcol * 32 + nt * 8 + (l & 7);
                int colh = k16 * 16 + (l >> 3) * 8;
                uint32_t addr = sb + row * 128 + ((colh * 2) ^ ((row & 7) * 16));
                asm volatile(
                    "ldmatrix.sync.aligned.m8n8.x2.shared.b16 {%0,%1}, [%2];"
                    : "=r"(b[nt][0]), "=r"(b[nt][1])
                    : "r"(addr));
            }
#pragma unroll
            for (int mt = 0; mt < 4; mt++)
#pragma unroll
                for (int nt = 0; nt < 4; nt++) {
                    asm volatile(
                        "mma.sync.aligned.m16n8k16.row.col.f32.f16.f16.f32 "
                        "{%0,%1,%2,%3}, {%4,%5,%6,%7}, {%8,%9}, {%0,%1,%2,%3};"
                        : "+f"(acc[mt][nt][0]), "+f"(acc[mt][nt][1]),
                          "+f"(acc[mt][nt][2]), "+f"(acc[mt][nt][3])
                        : "r"(a[mt][0]), "r"(a[mt][1]), "r"(a[mt][2]), "r"(a[mt][3]),
                          "r"(b[nt][0]), "r"(b[nt][1]));
                }
        }
        __syncthreads();
    }

    // Epilogue. c-frag: r0: (row=lane/4, col=2*(lane%4)); r1: col+1; r2/r3: row+8
#pragma unroll
    for (int mt = 0; mt < 4; mt++) {
#pragma unroll
        for (int nt = 0; nt < 4; nt++) {
            long r0 = bm0 + wrow * 64 + mt * 16 + (lane >> 2);
            long c0 = bn0 + wcol * 32 + nt * 8 + (lane & 3) * 2;
            if (EPI == 0) {
                float* C = (float*)Cout;
                *(float2*)(C + r0 * N + c0) =
                    make_float2(acc[mt][nt][0], acc[mt][nt][1]);
                *(float2*)(C + (r0 + 8) * N + c0) =
                    make_float2(acc[mt][nt][2], acc[mt][nt][3]);
            } else {
                __half* C = (__half*)Cout;
                float2 sA = *(const float2*)(aux + r0 * N + c0);
                float2 sB = *(const float2*)(aux + (r0 + 8) * N + c0);
                float h0 = (sA.x / (1.f + __expf(-sA.x))) * acc[mt][nt][0];
                float h1 = (sA.y / (1.f + __expf(-sA.y))) * acc[mt][nt][1];
                float h2 = (sB.x / (1.f + __expf(-sB.x))) * acc[mt][nt][2];
                float h3 = (sB.y / (1.f + __expf(-sB.y))) * acc[mt][nt][3];
                *(__half2*)(C + r0 * N + c0)       = __floats2half2_rn(h0, h1);
                *(__half2*)(C + (r0 + 8) * N + c0) = __floats2half2_rn(h2, h3);
            }
        }
    }
}

// ---------------------------------------------------------------------------
// Launch
// ---------------------------------------------------------------------------
extern "C" void kernel_launch(void* const* d_in, const int* in_sizes, int n_in,
                              void* d_out, int out_size) {
    const float* x   = (const float*)d_in[0];
    const int*   w1c = (const int*)d_in[1];
    const float* w1s = (const float*)d_in[2];
    const int*   w2c = (const int*)d_in[3];
    const float* w2s = (const float*)d_in[4];
    const int*   w3c = (const int*)d_in[5];
    const float* w3s = (const float*)d_in[6];

    int T = in_sizes[0] / D_DIM;  // 8192

    __half *w1h, *w2h, *w3h, *xh, *hbuf;
    float* s1;
    cudaGetSymbolAddress((void**)&w1h, g_w1);
    cudaGetSymbolAddress((void**)&w2h, g_w2);
    cudaGetSymbolAddress((void**)&w3h, g_w3);
    cudaGetSymbolAddress((void**)&xh, g_x);
    cudaGetSymbolAddress((void**)&s1, g_s1);
    cudaGetSymbolAddress((void**)&hbuf, g_h);

    const int SMEM = 2 * (BM + BN) * BK * 2;  // 64 KB
    cudaFuncSetAttribute(gemm_kernel<0>, cudaFuncAttributeMaxDynamicSharedMemorySize, SMEM);
    cudaFuncSetAttribute(gemm_kernel<1>, cudaFuncAttributeMaxDynamicSharedMemorySize, SMEM);

    // 1) Dequant weights to fp16
    int nW4 = (H_DIM * D_DIM) / 4;
    dequant_nf4_kernel<<<(nW4 + 255) / 256, 256>>>(w1c, w1s, w1h, nW4);
    dequant_nf4_kernel<<<(nW4 + 255) / 256, 256>>>(w2c, w2s, w2h, nW4);
    dequant_nf4_kernel<<<(nW4 + 255) / 256, 256>>>(w3c, w3s, w3h, nW4);

    // 2) x -> fp16
    int nX4 = (T * D_DIM) / 4;
    f32_to_f16_kernel<<<(nX4 + 255) / 256, 256>>>(x, xh, nX4);

    // 3) s1 = x @ w1^T (fp32)
    dim3 g1(H_DIM / BN, T / BM);
    gemm_kernel<0><<<g1, 256, SMEM>>>(xh, w1h, s1, nullptr, T, H_DIM, D_DIM);

    // 4) h = silu(s1) * (x @ w2^T)  (fp16)
    gemm_kernel<1><<<g1, 256, SMEM>>>(xh, w2h, hbuf, s1, T, H_DIM, D_DIM);

    // 5) out = h @ w3^T (fp32)
    dim3 g2(D_DIM / BN, T / BM);
    gemm_kernel<0><<<g2, 256, SMEM>>>(hbuf, w3h, d_out, nullptr, T, D_DIM, H_DIM);
}

// round 3
// speedup vs baseline: 1.0985x; 1.0985x over previous
#include <cuda_runtime.h>
#include <cuda_fp16.h>
#include <cstdint>

// Problem dims (fixed by the dataset)
#define D_DIM 4096
#define H_DIM 11008
#define T_MAX 8192

__device__ __constant__ float c_nf4[16] = {
    -1.0f, -0.6961928009986877f, -0.5250730514526367f, -0.39491748809814453f,
    -0.28444138169288635f, -0.18477343022823334f, -0.09105003625154495f, 0.0f,
    0.07958029955625534f, 0.16093020141124725f, 0.24611230194568634f,
    0.33791524171829224f, 0.44070982933044434f, 0.5626170039176941f,
    0.7229568362236023f, 1.0f};

// Scratch (static __device__ arrays: allocation-guard safe)
__device__ __align__(256) __half g_w1[(size_t)H_DIM * D_DIM];
__device__ __align__(256) __half g_w2[(size_t)H_DIM * D_DIM];
__device__ __align__(256) __half g_w3[(size_t)D_DIM * H_DIM];
__device__ __align__(256) __half g_x [(size_t)T_MAX * D_DIM];
__device__ __align__(256) __half g_s1[(size_t)T_MAX * H_DIM];
__device__ __align__(256) __half g_h [(size_t)T_MAX * H_DIM];

// ---------------------------------------------------------------------------
// Elementwise prep
// ---------------------------------------------------------------------------
__global__ void dequant_nf4_kernel(const int* __restrict__ codes,
                                   const float* __restrict__ scalers,
                                   __half* __restrict__ out, int n4) {
    int i = blockIdx.x * blockDim.x + threadIdx.x;
    if (i >= n4) return;
    int4 c = ((const int4*)codes)[i];
    float s = __ldg(&scalers[i >> 4]);
    __half2 h0 = __floats2half2_rn(c_nf4[c.x & 15] * s, c_nf4[c.y & 15] * s);
    __half2 h1 = __floats2half2_rn(c_nf4[c.z & 15] * s, c_nf4[c.w & 15] * s);
    ((__half2*)out)[2 * i]     = h0;
    ((__half2*)out)[2 * i + 1] = h1;
}

__global__ void f32_to_f16_kernel(const float* __restrict__ in,
                                  __half* __restrict__ out, int n4) {
    int i = blockIdx.x * blockDim.x + threadIdx.x;
    if (i >= n4) return;
    float4 v = ((const float4*)in)[i];
    ((__half2*)out)[2 * i]     = __floats2half2_rn(v.x, v.y);
    ((__half2*)out)[2 * i + 1] = __floats2half2_rn(v.z, v.w);
}

// ---------------------------------------------------------------------------
// GEMM: C[M,N] = A[M,K] * B[N,K]^T, fp16 in, fp32 acc
// CTA 128x128x64, 8 warps (2x4), warp tile 64x32, 3-stage cp.async pipeline.
// EPI=0: store fp16.  EPI=1: aux fp16, C=half(silu(aux)*acc).  EPI=2: store fp32.
// ---------------------------------------------------------------------------
#define BM 128
#define BN 128
#define BK 64
#define STG_A (BM * BK * 2)              // 16 KB
#define STG_BYTES ((BM + BN) * BK * 2)   // 32 KB
#define NSTAGE 3
#define SMEM_TOTAL (NSTAGE * STG_BYTES)  // 96 KB

__device__ __forceinline__ void cp_async16(uint32_t dst, const void* src) {
    asm volatile("cp.async.cg.shared.global [%0], [%1], 16;\n" ::"r"(dst), "l"(src));
}

template <int EPI>
__global__ void __launch_bounds__(256, 2) gemm_kernel(
    const __half* __restrict__ A, const __half* __restrict__ B,
    void* __restrict__ Cout, const __half* __restrict__ aux,
    int M, int N, int K) {
    extern __shared__ __align__(128) char smem_raw[];
    uint32_t smem_base = (uint32_t)__cvta_generic_to_shared(smem_raw);

    int tid  = threadIdx.x;
    int lane = tid & 31;
    int warp = tid >> 5;
    int wrow = warp >> 2;  // 0..1 -> 64 rows
    int wcol = warp & 3;   // 0..3 -> 32 cols

    long bm0 = (long)blockIdx.y * BM;
    long bn0 = (long)blockIdx.x * BN;

    const __half* Ablk = A + bm0 * K;
    const __half* Bblk = B + bn0 * K;

    int KT = K / BK;

    auto load_stage = [&](int kt, int s) {
        uint32_t sa = smem_base + s * STG_BYTES;
        uint32_t sbb = sa + STG_A;
        long koff = (long)kt * BK;
#pragma unroll
        for (int i = 0; i < 4; i++) {
            int e = i * 256 + tid;
            int row = e >> 3;
            int chunk = e & 7;
            uint32_t dst = sa + row * 128 + ((chunk * 16) ^ ((row & 7) * 16));
            cp_async16(dst, Ablk + (long)row * K + koff + chunk * 8);
        }
#pragma unroll
        for (int i = 0; i < 4; i++) {
            int e = i * 256 + tid;
            int row = e >> 3;
            int chunk = e & 7;
            uint32_t dst = sbb + row * 128 + ((chunk * 16) ^ ((row & 7) * 16));
            cp_async16(dst, Bblk + (long)row * K + koff + chunk * 8);
        }
    };

    float acc[4][4][4];
#pragma unroll
    for (int mt = 0; mt < 4; mt++)
#pragma unroll
        for (int nt = 0; nt < 4; nt++)
#pragma unroll
            for (int r = 0; r < 4; r++) acc[mt][nt][r] = 0.f;

    // Prologue: stages 0 and 1 in flight
    load_stage(0, 0);
    asm volatile("cp.async.commit_group;\n");
    load_stage(1, 1);
    asm volatile("cp.async.commit_group;\n");

    // Precompute per-thread ldmatrix shared addresses (stage-relative)
    int a_row = wrow * 64 + (lane & 15);
    int a_colh = (lane >> 4) * 8;
    uint32_t a_off = a_row * 128 + ((a_colh * 2) ^ ((a_row & 7) * 16));
    int b_row = wcol * 32 + ((lane >> 4) << 3) + (lane & 7);
    int b_colh = ((lane >> 3) & 1) * 8;
    uint32_t b_off = STG_A + b_row * 128 + ((b_colh * 2) ^ ((b_row & 7) * 16));

    for (int kt = 0; kt < KT; kt++) {
        asm volatile("cp.async.wait_group 1;\n");
        __syncthreads();

        // Issue loads for stage kt+2 (slot freed by all warps at this barrier)
        if (kt + 2 < KT) load_stage(kt + 2, (kt + 2) % NSTAGE);
        asm volatile("cp.async.commit_group;\n");

        uint32_t st = smem_base + (kt % NSTAGE) * STG_BYTES;
#pragma unroll
        for (int k16 = 0; k16 < BK / 16; k16++) {
            uint32_t a[4][4];
            uint32_t b[4][2];
#pragma unroll
            for (int mt = 0; mt < 4; mt++) {
                uint32_t addr = st + a_off + mt * 16 * 128 + ((k16 * 32) ^ 0);
                // swizzle: col bytes = (k16*16 + a_colh)*2 ; recompute properly:
                int colh = k16 * 16 + a_colh;
                int row = wrow * 64 + mt * 16 + (lane & 15);
                addr = st + row * 128 + ((colh * 2) ^ ((row & 7) * 16));
                asm volatile(
                    "ldmatrix.sync.aligned.m8n8.x4.shared.b16 {%0,%1,%2,%3}, [%4];"
                    : "=r"(a[mt][0]), "=r"(a[mt][1]), "=r"(a[mt][2]), "=r"(a[mt][3])
                    : "r"(addr));
            }
#pragma unroll
            for (int p = 0; p < 2; p++) {
                int row = wcol * 32 + p * 16 + ((lane >> 4) << 3) + (lane & 7);
                int colh = k16 * 16 + b_colh;
                uint32_t addr = st + STG_A + row * 128 + ((colh * 2) ^ ((row & 7) * 16));
                asm volatile(
                    "ldmatrix.sync.aligned.m8n8.x4.shared.b16 {%0,%1,%2,%3}, [%4];"
                    : "=r"(b[2 * p][0]), "=r"(b[2 * p][1]),
                      "=r"(b[2 * p + 1][0]), "=r"(b[2 * p + 1][1])
                    : "r"(addr));
            }
#pragma unroll
            for (int mt = 0; mt < 4; mt++)
#pragma unroll
                for (int nt = 0; nt < 4; nt++) {
                    asm volatile(
                        "mma.sync.aligned.m16n8k16.row.col.f32.f16.f16.f32 "
                        "{%0,%1,%2,%3}, {%4,%5,%6,%7}, {%8,%9}, {%0,%1,%2,%3};"
                        : "+f"(acc[mt][nt][0]), "+f"(acc[mt][nt][1]),
                          "+f"(acc[mt][nt][2]), "+f"(acc[mt][nt][3])
                        : "r"(a[mt][0]), "r"(a[mt][1]), "r"(a[mt][2]), "r"(a[mt][3]),
                          "r"(b[nt][0]), "r"(b[nt][1]));
                }
        }
    }

    // Epilogue. c-frag: r0: (row=lane/4, col=2*(lane%4)); r1: col+1; r2/r3: row+8
#pragma unroll
    for (int mt = 0; mt < 4; mt++) {
#pragma unroll
        for (int nt = 0; nt < 4; nt++) {
            long r0 = bm0 + wrow * 64 + mt * 16 + (lane >> 2);
            long c0 = bn0 + wcol * 32 + nt * 8 + (lane & 3) * 2;
            if (EPI == 0) {
                __half* C = (__half*)Cout;
                *(__half2*)(C + r0 * N + c0) =
                    __floats2half2_rn(acc[mt][nt][0], acc[mt][nt][1]);
                *(__half2*)(C + (r0 + 8) * N + c0) =
                    __floats2half2_rn(acc[mt][nt][2], acc[mt][nt][3]);
            } else if (EPI == 1) {
                __half* C = (__half*)Cout;
                __half2 sa2 = *(const __half2*)(aux + r0 * N + c0);
                __half2 sb2 = *(const __half2*)(aux + (r0 + 8) * N + c0);
                float s0 = __half2float(sa2.x), s1v = __half2float(sa2.y);
                float s2 = __half2float(sb2.x), s3 = __half2float(sb2.y);
                float h0 = s0 / (1.f + __expf(-s0)) * acc[mt][nt][0];
                float h1 = s1v / (1.f + __expf(-s1v)) * acc[mt][nt][1];
                float h2 = s2 / (1.f + __expf(-s2)) * acc[mt][nt][2];
                float h3 = s3 / (1.f + __expf(-s3)) * acc[mt][nt][3];
                *(__half2*)(C + r0 * N + c0)       = __floats2half2_rn(h0, h1);
                *(__half2*)(C + (r0 + 8) * N + c0) = __floats2half2_rn(h2, h3);
            } else {
                float* C = (float*)Cout;
                *(float2*)(C + r0 * N + c0) =
                    make_float2(acc[mt][nt][0], acc[mt][nt][1]);
                *(float2*)(C + (r0 + 8) * N + c0) =
                    make_float2(acc[mt][nt][2], acc[mt][nt][3]);
            }
        }
    }
}

// ---------------------------------------------------------------------------
// Launch
// ---------------------------------------------------------------------------
extern "C" void kernel_launch(void* const* d_in, const int* in_sizes, int n_in,
                              void* d_out, int out_size) {
    const float* x = (const float*)d_in[0];
    const int* w1c = (const int*)d_in[1];
    const float* w1s = (const float*)d_in[2];
    const int* w2c = (const int*)d_in[3];
    const float* w2s = (const float*)d_in[4];
    const int* w3c = (const int*)d_in[5];
    const float* w3s = (const float*)d_in[6];

    int T = in_sizes[0] / D_DIM;  // 8192

    __half *w1h, *w2h, *w3h, *xh, *s1h, *hbuf;
    cudaGetSymbolAddress((void**)&w1h, g_w1);
    cudaGetSymbolAddress((void**)&w2h, g_w2);
    cudaGetSymbolAddress((void**)&w3h, g_w3);
    cudaGetSymbolAddress((void**)&xh, g_x);
    cudaGetSymbolAddress((void**)&s1h, g_s1);
    cudaGetSymbolAddress((void**)&hbuf, g_h);

    cudaFuncSetAttribute(gemm_kernel<0>, cudaFuncAttributeMaxDynamicSharedMemorySize, SMEM_TOTAL);
    cudaFuncSetAttribute(gemm_kernel<1>, cudaFuncAttributeMaxDynamicSharedMemorySize, SMEM_TOTAL);
    cudaFuncSetAttribute(gemm_kernel<2>, cudaFuncAttributeMaxDynamicSharedMemorySize, SMEM_TOTAL);

    // 1) Dequant weights to fp16
    int nW4 = (H_DIM * D_DIM) / 4;
    dequant_nf4_kernel<<<(nW4 + 255) / 256, 256>>>(w1c, w1s, w1h, nW4);
    dequant_nf4_kernel<<<(nW4 + 255) / 256, 256>>>(w2c, w2s, w2h, nW4);
    dequant_nf4_kernel<<<(nW4 + 255) / 256, 256>>>(w3c, w3s, w3h, nW4);

    // 2) x -> fp16
    int nX4 = (T * D_DIM) / 4;
    f32_to_f16_kernel<<<(nX4 + 255) / 256, 256>>>(x, xh, nX4);

    // 3) s1 = x @ w1^T (fp16)
    dim3 g1(H_DIM / BN, T / BM);
    gemm_kernel<0><<<g1, 256, SMEM_TOTAL>>>(xh, w1h, s1h, nullptr, T, H_DIM, D_DIM);

    // 4) h = silu(s1) * (x @ w2^T)  (fp16)
    gemm_kernel<1><<<g1, 256, SMEM_TOTAL>>>(xh, w2h, hbuf, s1h, T, H_DIM, D_DIM);

    // 5) out = h @ w3^T (fp32)
    dim3 g2(D_DIM / BN, T / BM);
    gemm_kernel<2><<<g2, 256, SMEM_TOTAL>>>(hbuf, w3h, d_out, nullptr, T, D_DIM, H_DIM);
}